// round 3
// baseline (speedup 1.0000x reference)
#include <cuda_runtime.h>
#include <cuda_bf16.h>

// dynFilter: out[b,1,h,w] = tanh( sum_{c,ky,kx} x[b,c,h+ky-2,w+kx-2] * filt[b, c*25+ky*5+kx, h, w] )
// x [8,4,256,256] f32, filt [8,100,256,256] f32, out [8,1,256,256] f32.
// HBM-bound (~210 MB compulsory, floor ~26us @8TB/s).
// R2: 39.7us @ DRAM 73.9%, occ stuck at 38% (regs=64 binding).
// R3: per-ky window load (xr 40regs -> 8regs, zero reuse lost since each smem
//     row is consumed by exactly one ky), __launch_bounds__(128,12) -> 12 CTA/SM,
//     tanh.approx.f32 epilogue.

#define KK 5
#define PADK 2
#define CC 4
#define HH 256
#define WW 256
#define TILE_H 4
#define TILE_W 128
#define NROWS (TILE_H + 2 * PADK)        // 8 halo rows
#define NCOLS (TILE_W + 2 * PADK)        // 132 halo cols
#define NCOLS_PAD 136                    // 16B-aligned row stride

__device__ __forceinline__ float tanh_approx(float v) {
    float r;
    asm("tanh.approx.f32 %0, %1;" : "=f"(r) : "f"(v));
    return r;
}

__global__ __launch_bounds__(128, 12)
void dynfilter_kernel(const float* __restrict__ x,
                      const float* __restrict__ filt,
                      float* __restrict__ out)
{
    const int b     = blockIdx.z;
    const int whalf = blockIdx.y;            // 0..1
    const int h0    = blockIdx.x * TILE_H;   // tile row base
    const int w0    = whalf * TILE_W;        // tile col base
    const int tid   = threadIdx.x;

    __shared__ __align__(16) float xs[CC][NROWS][NCOLS_PAD];

    // Cooperative halo load: rows h0-2..h0+5, cols w0-2..w0+129 (zero pad OOB).
    #pragma unroll
    for (int it = 0; it < (CC * NROWS * NCOLS + 127) / 128; ++it) {
        int idx = it * 128 + tid;
        if (idx < CC * NROWS * NCOLS) {
            int c   = idx / (NROWS * NCOLS);
            int rem = idx % (NROWS * NCOLS);
            int r   = rem / NCOLS;
            int col = rem % NCOLS;
            int gr = h0 - PADK + r;
            int gc = w0 - PADK + col;
            float v = 0.0f;
            if (gr >= 0 && gr < HH && gc >= 0 && gc < WW)
                v = x[(((b * CC) + c) * HH + gr) * WW + gc];
            xs[c][r][col] = v;
        }
    }
    __syncthreads();

    const int hr = tid >> 5;       // 0..3 row within tile
    const int q  = tid & 31;       // 0..31 float4 column within tile
    const int h  = h0 + hr;
    const int wl = q << 2;         // local smem col of window start (= w-2 incl. halo)

    float acc0 = 0.f, acc1 = 0.f, acc2 = 0.f, acc3 = 0.f;

    const float4* __restrict__ filt4 = (const float4*)filt;
    const long plane = (long)(HH * WW / 4);  // 16384 float4 per plane
    long fbase = ((long)b * (CC * KK * KK) * HH + h) * (WW / 4) + (whalf * 32 + q);

    #pragma unroll
    for (int c = 0; c < CC; ++c) {
        #pragma unroll
        for (int ky = 0; ky < KK; ++ky) {
            // Batch the 5 filt LDG.128 for this (c,ky) row (MLP=5 per warp).
            float4 f[KK];
            #pragma unroll
            for (int kx = 0; kx < KK; ++kx) {
                const int p = (c * KK + ky) * KK + kx;
                f[kx] = __ldg(&filt4[fbase + (long)p * plane]);
            }
            // 8-float window row via two conflict-free LDS.128 (consumed once).
            float xr[8];
            {
                float4 a  = *(const float4*)&xs[c][hr + ky][wl];
                float4 bb = *(const float4*)&xs[c][hr + ky][wl + 4];
                xr[0] = a.x;  xr[1] = a.y;  xr[2] = a.z;  xr[3] = a.w;
                xr[4] = bb.x; xr[5] = bb.y; xr[6] = bb.z; xr[7] = bb.w;
            }
            #pragma unroll
            for (int kx = 0; kx < KK; ++kx) {
                acc0 = fmaf(xr[kx + 0], f[kx].x, acc0);
                acc1 = fmaf(xr[kx + 1], f[kx].y, acc1);
                acc2 = fmaf(xr[kx + 2], f[kx].z, acc2);
                acc3 = fmaf(xr[kx + 3], f[kx].w, acc3);
            }
        }
    }

    float4 o;
    o.x = tanh_approx(acc0);
    o.y = tanh_approx(acc1);
    o.z = tanh_approx(acc2);
    o.w = tanh_approx(acc3);
    ((float4*)out)[((long)b * HH + h) * (WW / 4) + whalf * 32 + q] = o;
}

extern "C" void kernel_launch(void* const* d_in, const int* in_sizes, int n_in,
                              void* d_out, int out_size)
{
    const float* x    = (const float*)d_in[0];   // [8,4,256,256]
    const float* filt = (const float*)d_in[1];   // [8,100,256,256]
    float* out        = (float*)d_out;           // [8,1,256,256]

    dim3 grid(HH / TILE_H, WW / TILE_W, 8);   // 64 x 2 x 8 = 1024 CTAs
    dim3 block(128);
    dynfilter_kernel<<<grid, block>>>(x, filt, out);
}

// round 4
// speedup vs baseline: 1.3114x; 1.3114x over previous
#include <cuda_runtime.h>
#include <cuda_bf16.h>

// dynFilter: out[b,1,h,w] = tanh( sum_{c,ky,kx} x[b,c,h+ky-2,w+kx-2] * filt[b, c*25+ky*5+kx, h, w] )
// x [8,4,256,256] f32, filt [8,100,256,256] f32, out [8,1,256,256] f32.
// HBM-bound, ~210 MB compulsory DRAM traffic.
// R2 best: 39.7us, DRAM 73.9%, regs=64 (launch_bounds cap).
// R3 lesson: cutting regs kills ptxas pipelining -> MLP collapse (58% DRAM).
// R4: same R2 structure, launch_bounds(128,7) -> 72-reg budget matching the
//     grid's 6.9 CTAs/SM, streaming loads for filt, tanh.approx epilogue.

#define KK 5
#define PADK 2
#define CC 4
#define HH 256
#define WW 256
#define TILE_H 4
#define TILE_W 128
#define NROWS (TILE_H + 2 * PADK)        // 8 halo rows
#define NCOLS (TILE_W + 2 * PADK)        // 132 halo cols
#define NCOLS_PAD 136                    // 16B-aligned row stride

__device__ __forceinline__ float tanh_approx(float v) {
    float r;
    asm("tanh.approx.f32 %0, %1;" : "=f"(r) : "f"(v));
    return r;
}

__global__ __launch_bounds__(128, 7)
void dynfilter_kernel(const float* __restrict__ x,
                      const float* __restrict__ filt,
                      float* __restrict__ out)
{
    const int b     = blockIdx.z;
    const int whalf = blockIdx.y;            // 0..1
    const int h0    = blockIdx.x * TILE_H;   // tile row base
    const int w0    = whalf * TILE_W;        // tile col base
    const int tid   = threadIdx.x;

    __shared__ __align__(16) float xs[CC][NROWS][NCOLS_PAD];

    // Cooperative halo load: rows h0-2..h0+5, cols w0-2..w0+129 (zero pad OOB).
    #pragma unroll
    for (int it = 0; it < (CC * NROWS * NCOLS + 127) / 128; ++it) {
        int idx = it * 128 + tid;
        if (idx < CC * NROWS * NCOLS) {
            int c   = idx / (NROWS * NCOLS);
            int rem = idx % (NROWS * NCOLS);
            int r   = rem / NCOLS;
            int col = rem % NCOLS;
            int gr = h0 - PADK + r;
            int gc = w0 - PADK + col;
            float v = 0.0f;
            if (gr >= 0 && gr < HH && gc >= 0 && gc < WW)
                v = x[(((b * CC) + c) * HH + gr) * WW + gc];
            xs[c][r][col] = v;
        }
    }
    __syncthreads();

    const int hr = tid >> 5;       // 0..3 row within tile
    const int q  = tid & 31;       // 0..31 float4 column within tile
    const int h  = h0 + hr;
    const int wl = q << 2;         // local smem col of window start (w-2 incl halo)

    float acc0 = 0.f, acc1 = 0.f, acc2 = 0.f, acc3 = 0.f;

    const float4* __restrict__ filt4 = (const float4*)filt;
    const long plane = (long)(HH * WW / 4);  // 16384 float4 per plane
    long fbase = ((long)b * (CC * KK * KK) * HH + h) * (WW / 4) + (whalf * 32 + q);

    #pragma unroll
    for (int c = 0; c < CC; ++c) {
        // Full 5x8 register window via conflict-free LDS.128 (large reorder
        // window for ptxas to hoist smem reads and pipeline LDGs).
        float xr[KK][8];
        #pragma unroll
        for (int ky = 0; ky < KK; ++ky) {
            float4 a  = *(const float4*)&xs[c][hr + ky][wl];
            float4 bb = *(const float4*)&xs[c][hr + ky][wl + 4];
            xr[ky][0] = a.x;  xr[ky][1] = a.y;  xr[ky][2] = a.z;  xr[ky][3] = a.w;
            xr[ky][4] = bb.x; xr[ky][5] = bb.y; xr[ky][6] = bb.z; xr[ky][7] = bb.w;
        }
        #pragma unroll
        for (int ky = 0; ky < KK; ++ky) {
            // Batch the 5 streaming filt LDG.128 for this ky row.
            float4 f[KK];
            #pragma unroll
            for (int kx = 0; kx < KK; ++kx) {
                const int p = (c * KK + ky) * KK + kx;
                f[kx] = __ldcs(&filt4[fbase + (long)p * plane]);
            }
            #pragma unroll
            for (int kx = 0; kx < KK; ++kx) {
                acc0 = fmaf(xr[ky][kx + 0], f[kx].x, acc0);
                acc1 = fmaf(xr[ky][kx + 1], f[kx].y, acc1);
                acc2 = fmaf(xr[ky][kx + 2], f[kx].z, acc2);
                acc3 = fmaf(xr[ky][kx + 3], f[kx].w, acc3);
            }
        }
    }

    float4 o;
    o.x = tanh_approx(acc0);
    o.y = tanh_approx(acc1);
    o.z = tanh_approx(acc2);
    o.w = tanh_approx(acc3);
    ((float4*)out)[((long)b * HH + h) * (WW / 4) + whalf * 32 + q] = o;
}

extern "C" void kernel_launch(void* const* d_in, const int* in_sizes, int n_in,
                              void* d_out, int out_size)
{
    const float* x    = (const float*)d_in[0];   // [8,4,256,256]
    const float* filt = (const float*)d_in[1];   // [8,100,256,256]
    float* out        = (float*)d_out;           // [8,1,256,256]

    dim3 grid(HH / TILE_H, WW / TILE_W, 8);   // 64 x 2 x 8 = 1024 CTAs
    dim3 block(128);
    dynfilter_kernel<<<grid, block>>>(x, filt, out);
}